// round 10
// baseline (speedup 1.0000x reference)
#include <cuda_runtime.h>
#include <cuda_fp16.h>
#include <cstdint>

#define E_MAX 100096
#define IN_F  256
#define HID   128

// scratch (device globals = allowed scratch)
__device__ __half g_th[(size_t)E_MAX * HID];    // fp16 t (self + gather)

__device__ __forceinline__ uint32_t smem_u32(const void* p) {
    uint32_t a;
    asm("{ .reg .u64 t; cvta.to.shared.u64 t, %1; cvt.u32.u64 %0, t; }" : "=r"(a) : "l"(p));
    return a;
}
__device__ __forceinline__ void ldsm_x4(uint32_t& r0, uint32_t& r1, uint32_t& r2,
                                        uint32_t& r3, uint32_t addr) {
    asm volatile("ldmatrix.sync.aligned.m8n8.x4.shared.b16 {%0,%1,%2,%3}, [%4];"
                 : "=r"(r0), "=r"(r1), "=r"(r2), "=r"(r3) : "r"(addr));
}
__device__ __forceinline__ void mma16816(float* c, uint32_t a0, uint32_t a1,
                                         uint32_t a2, uint32_t a3,
                                         uint32_t b0, uint32_t b1) {
    asm volatile(
        "mma.sync.aligned.m16n8k16.row.col.f32.f16.f16.f32 "
        "{%0,%1,%2,%3}, {%4,%5,%6,%7}, {%8,%9}, {%0,%1,%2,%3};"
        : "+f"(c[0]), "+f"(c[1]), "+f"(c[2]), "+f"(c[3])
        : "r"(a0), "r"(a1), "r"(a2), "r"(a3), "r"(b0), "r"(b1));
}
__device__ __forceinline__ void cp_async16(uint32_t dst, const void* src) {
    asm volatile("cp.async.cg.shared.global [%0], [%1], 16;" :: "r"(dst), "l"(src));
}
#define CP_COMMIT() asm volatile("cp.async.commit_group;" ::: "memory")
#define CP_WAIT0()  asm volatile("cp.async.wait_group 0;" ::: "memory")

// =====================================================================
// t = Xh @ Wh + b : single-pass fp16 HMMA, fp32 accum.
// CTA = 128x128, 8 warps (4m x 2n), BK=32, cp.async double-buffered
// X fp32 AND W fp32 staging; in-CTA convert (A) + transpose-convert (B).
// No separate W-prep kernel.
// =====================================================================
#define BK 32
#define STR 40                        // smem row stride (halves): 80 B

#define SM_XF 0                       // X fp32 staging: 2 x 16384
#define SM_WF 32768                   // W fp32 staging: 2 x 16384
#define SM_AH 65536                   // A fp16 tile [128][STR] = 10240
#define SM_B  75776                   // B fp16 tile [128][STR] = 10240
#define SMEM_BYTES 86016

__device__ __forceinline__ void prefetch_chunk(
    uint32_t smb, int buf,
    const float4* __restrict__ X4,
    const float4* __restrict__ W4,
    int tid, int rowBase, int kc, int E)
{
    uint32_t xdst = smb + SM_XF + buf * 16384;
#pragma unroll
    for (int it = 0; it < 4; ++it) {
        int i = it * 256 + tid;           // 1024 float4
        int r = i >> 3, f = i & 7;
        int grow = rowBase + r;
        if (grow >= E) grow = E - 1;
        cp_async16(xdst + i * 16, X4 + grow * (IN_F / 4) + kc * 8 + f);
    }
    uint32_t wdst = smb + SM_WF + buf * 16384;
#pragma unroll
    for (int it = 0; it < 4; ++it) {
        int i = it * 256 + tid;           // 1024 float4: [k=32][n=128 -> 32 f4]
        int k = i >> 5, q = i & 31;
        cp_async16(wdst + i * 16, W4 + (kc * 32 + k) * (HID / 4) + q);
    }
    CP_COMMIT();
}

// A: staged X fp32 [r][k32] -> sA fp16 [r][k]
__device__ __forceinline__ void convert_A(char* smem, int buf, int tid) {
    const float4* xf = (const float4*)(smem + SM_XF + buf * 16384);
    __half* sAh = (__half*)(smem + SM_AH);
#pragma unroll
    for (int it = 0; it < 4; ++it) {
        int i = it * 256 + tid;
        int r = i >> 3, f = i & 7;
        float4 v = xf[i];
        uint2 hp;
        hp.x = ((uint32_t)__half_as_ushort(__float2half_rn(v.y)) << 16)
             |  __half_as_ushort(__float2half_rn(v.x));
        hp.y = ((uint32_t)__half_as_ushort(__float2half_rn(v.w)) << 16)
             |  __half_as_ushort(__float2half_rn(v.z));
        *(uint2*)(sAh + r * STR + f * 4) = hp;
    }
}

// B: staged W fp32 [k=32][n=128] -> sB fp16 [n][k]  (transpose-convert)
__device__ __forceinline__ void convert_B(char* smem, int buf, int tid) {
    const float* wf = (const float*)(smem + SM_WF + buf * 16384);
    __half* sB = (__half*)(smem + SM_B);
    int n  = tid & 127;
    int k0 = (tid >> 7) * 16;            // 0 or 16
    uint32_t pk[8];
#pragma unroll
    for (int kk = 0; kk < 16; kk += 2) {
        __half h0 = __float2half_rn(wf[(k0 + kk)     * HID + n]);
        __half h1 = __float2half_rn(wf[(k0 + kk + 1) * HID + n]);
        pk[kk >> 1] = ((uint32_t)__half_as_ushort(h1) << 16) | __half_as_ushort(h0);
    }
    uint4* dst = (uint4*)(sB + n * STR + k0);   // n*80 + k0*2 bytes: 16B-aligned
    dst[0] = make_uint4(pk[0], pk[1], pk[2], pk[3]);
    dst[1] = make_uint4(pk[4], pk[5], pk[6], pk[7]);
}

__global__ __launch_bounds__(256, 2)
void gemm_mma_kernel(const float* __restrict__ X,
                     const float* __restrict__ W,
                     const float* __restrict__ bias,
                     int E) {
    extern __shared__ char smem[];

    const int tid  = threadIdx.x;
    const int wid  = tid >> 5;
    const int lane = tid & 31;
    const int wm   = wid & 3;
    const int wn   = wid >> 2;
    const int rowBase = blockIdx.x * 128;

    float acc[2][8][4];
#pragma unroll
    for (int mi = 0; mi < 2; ++mi)
#pragma unroll
        for (int ni = 0; ni < 8; ++ni)
#pragma unroll
            for (int q = 0; q < 4; ++q) acc[mi][ni][q] = 0.f;

    const float4* X4 = (const float4*)X;
    const float4* W4 = (const float4*)W;

    const uint32_t smb = smem_u32(smem);

    const int lrow = (lane & 7) + ((lane >> 3) & 1) * 8;
    const int lkof = ((lane >> 4) & 1) * 8;

    prefetch_chunk(smb, 0, X4, W4, tid, rowBase, 0, E);

    for (int kc = 0; kc < IN_F / BK; ++kc) {
        const int buf = kc & 1;

        CP_WAIT0();
        __syncthreads();                 // staged data visible; tiles free

        convert_A(smem, buf, tid);
        convert_B(smem, buf, tid);

        if (kc + 1 < IN_F / BK)
            prefetch_chunk(smb, buf ^ 1, X4, W4, tid, rowBase, kc + 1, E);

        __syncthreads();                 // tiles ready

        const uint32_t ah_b = smb + SM_AH;
        const uint32_t bh_b = smb + SM_B;

#pragma unroll
        for (int ks = 0; ks < 2; ++ks) {
            const int kk = ks * 16;
            uint32_t af[2][4], bf[4][4];

#pragma unroll
            for (int mi = 0; mi < 2; ++mi)
                ldsm_x4(af[mi][0], af[mi][1], af[mi][2], af[mi][3],
                        ah_b + ((wm * 32 + mi * 16 + lrow) * STR + kk + lkof) * 2);
#pragma unroll
            for (int bi = 0; bi < 4; ++bi)
                ldsm_x4(bf[bi][0], bf[bi][1], bf[bi][2], bf[bi][3],
                        bh_b + ((wn * 64 + bi * 16 + lrow) * STR + kk + lkof) * 2);
#pragma unroll
            for (int mi = 0; mi < 2; ++mi)
#pragma unroll
                for (int bi = 0; bi < 4; ++bi) {
                    mma16816(acc[mi][bi * 2 + 0], af[mi][0], af[mi][1], af[mi][2], af[mi][3],
                             bf[bi][0], bf[bi][2]);
                    mma16816(acc[mi][bi * 2 + 1], af[mi][0], af[mi][1], af[mi][2], af[mi][3],
                             bf[bi][1], bf[bi][3]);
                }
        }
        __syncthreads();                 // protect tiles before next convert
    }

    // ---- epilogue: + bias, store fp16 t ----
    const int gid = lane >> 2;
    const int cid = (lane & 3) * 2;
#pragma unroll
    for (int mi = 0; mi < 2; ++mi) {
        int row0 = rowBase + wm * 32 + mi * 16 + gid;
#pragma unroll
        for (int ni = 0; ni < 8; ++ni) {
            int col = wn * 64 + ni * 8 + cid;
            float b0 = __ldg(bias + col), b1 = __ldg(bias + col + 1);
            if (row0 < E) {
                *(__half2*)(g_th + (size_t)row0 * HID + col) =
                    __floats2half2_rn(acc[mi][ni][0] + b0, acc[mi][ni][1] + b1);
            }
            if (row0 + 8 < E) {
                *(__half2*)(g_th + (size_t)(row0 + 8) * HID + col) =
                    __floats2half2_rn(acc[mi][ni][2] + b0, acc[mi][ni][3] + b1);
            }
        }
    }
}

// =====================================================================
// out[i] = fp16(t[i]) + sum_k fp16(t[nbr[i][k]])  (fp32 accumulate/write)
// =====================================================================
__global__ __launch_bounds__(256)
void gather_sum_kernel(const int* __restrict__ nbr,
                       float* __restrict__ out,
                       int E) {
    int gtid = blockIdx.x * blockDim.x + threadIdx.x;
    int e    = gtid >> 5;
    int lane = threadIdx.x & 31;
    if (e >= E) return;

    const uint2* H2 = (const uint2*)g_th;    // 4 halves per uint2; 32 per row

    int j = 0;
    if (lane < 16) j = nbr[e * 16 + lane];

    uint2 s = H2[e * 32 + lane];             // self
    float2 sa = __half22float2(*(const __half2*)&s.x);
    float2 sb = __half22float2(*(const __half2*)&s.y);
    float4 acc = {sa.x, sa.y, sb.x, sb.y};

    uint2 v[16];
#pragma unroll
    for (int k = 0; k < 16; ++k) {
        int n = __shfl_sync(0xffffffffu, j, k);
        v[k] = H2[n * 32 + lane];
    }
#pragma unroll
    for (int k = 0; k < 16; ++k) {
        float2 a = __half22float2(*(const __half2*)&v[k].x);
        float2 b = __half22float2(*(const __half2*)&v[k].y);
        acc.x += a.x;
        acc.y += a.y;
        acc.z += b.x;
        acc.w += b.y;
    }
    ((float4*)out)[e * 32 + lane] = acc;
}

extern "C" void kernel_launch(void* const* d_in, const int* in_sizes, int n_in,
                              void* d_out, int out_size) {
    const float* X   = (const float*)d_in[0];   // edge_feats [E, 256]
    const int*   nbr = (const int*)  d_in[1];   // neighbors  [E, 16]
    const float* W   = (const float*)d_in[2];   // W          [256, 128]
    const float* b   = (const float*)d_in[3];   // b          [128]
    float* out = (float*)d_out;                 // [E, 128]

    int E = in_sizes[0] / IN_F;

    cudaFuncSetAttribute(gemm_mma_kernel,
                         cudaFuncAttributeMaxDynamicSharedMemorySize, SMEM_BYTES);

    int gblocks = (E + 127) / 128;
    gemm_mma_kernel<<<gblocks, 256, SMEM_BYTES>>>(X, W, b, E);

    long long threads = (long long)E * 32;      // one warp per edge
    int blocks2 = (int)((threads + 255) / 256);
    gather_sum_kernel<<<blocks2, 256>>>(nbr, out, E);
}

// round 11
// speedup vs baseline: 1.0585x; 1.0585x over previous
#include <cuda_runtime.h>
#include <cuda_fp16.h>
#include <cstdint>

#define E_MAX 100096
#define IN_F  256
#define HID   128

// scratch (device globals = allowed scratch)
__device__ __half g_th[(size_t)E_MAX * HID];    // fp16 t (self + gather)
__device__ __half g_wh[HID * IN_F];             // W transposed [n][k], fp16

__device__ __forceinline__ uint32_t smem_u32(const void* p) {
    uint32_t a;
    asm("{ .reg .u64 t; cvta.to.shared.u64 t, %1; cvt.u32.u64 %0, t; }" : "=r"(a) : "l"(p));
    return a;
}
__device__ __forceinline__ void ldsm_x4(uint32_t& r0, uint32_t& r1, uint32_t& r2,
                                        uint32_t& r3, uint32_t addr) {
    asm volatile("ldmatrix.sync.aligned.m8n8.x4.shared.b16 {%0,%1,%2,%3}, [%4];"
                 : "=r"(r0), "=r"(r1), "=r"(r2), "=r"(r3) : "r"(addr));
}
__device__ __forceinline__ void mma16816(float* c, uint32_t a0, uint32_t a1,
                                         uint32_t a2, uint32_t a3,
                                         uint32_t b0, uint32_t b1) {
    asm volatile(
        "mma.sync.aligned.m16n8k16.row.col.f32.f16.f16.f32 "
        "{%0,%1,%2,%3}, {%4,%5,%6,%7}, {%8,%9}, {%0,%1,%2,%3};"
        : "+f"(c[0]), "+f"(c[1]), "+f"(c[2]), "+f"(c[3])
        : "r"(a0), "r"(a1), "r"(a2), "r"(a3), "r"(b0), "r"(b1));
}
__device__ __forceinline__ void cp_async16(uint32_t dst, const void* src) {
    asm volatile("cp.async.cg.shared.global [%0], [%1], 16;" :: "r"(dst), "l"(src));
}
#define CP_COMMIT() asm volatile("cp.async.commit_group;" ::: "memory")
#define CP_WAIT0()  asm volatile("cp.async.wait_group 0;" ::: "memory")

// =====================================================================
// W transpose -> fp16 (one-shot tiny kernel; cheaper than in-GEMM fold, R9)
// =====================================================================
__global__ void wconv_kernel(const float* __restrict__ W) {
    int i = blockIdx.x * 256 + threadIdx.x;
    if (i >= IN_F * HID) return;
    int k = i >> 7, n = i & 127;
    g_wh[n * IN_F + k] = __float2half_rn(W[i]);
}

// =====================================================================
// t = Xh @ Wh + b : single-pass fp16 HMMA, fp32 accum  (R8 structure)
// CTA = 128x128, 8 warps (4m x 2n), BK=32, cp.async double-buffered.
// =====================================================================
#define BK 32
#define STR 40                       // smem row stride (halves): 80 B
#define TILE_B (128 * STR * 2)       // 10240 B per fp16 tile

#define SM_XF 0                      // X fp32 staging: 2 x 16384
#define SM_AH 32768                  // A fp16 tile (single)
#define SM_B  43008                  // B tiles: 2 x 10240 (double-buffered)
#define SMEM_BYTES (43008 + 20480)   // 63488

__device__ __forceinline__ void prefetch_chunk(
    uint32_t smb, int buf,
    const float4* __restrict__ X4,
    const uint4* __restrict__ bh4,
    int tid, int rowBase, int kc, int E)
{
    uint32_t xdst = smb + SM_XF + buf * 16384;
#pragma unroll
    for (int it = 0; it < 4; ++it) {
        int i = it * 256 + tid;          // 1024 float4
        int r = i >> 3, f = i & 7;
        int grow = rowBase + r;
        if (grow >= E) grow = E - 1;
        cp_async16(xdst + i * 16, X4 + grow * (IN_F / 4) + kc * 8 + f);
    }
    uint32_t bdst = smb + SM_B + buf * TILE_B;
#pragma unroll
    for (int it = 0; it < 2; ++it) {
        int i = it * 256 + tid;          // 512 uint4
        int n = i >> 2, q = i & 3;
        uint32_t off = (uint32_t)(n * STR + q * 8) * 2;    // 16B-aligned
        cp_async16(bdst + off, bh4 + n * 32 + kc * 4 + q);
    }
    CP_COMMIT();
}

__device__ __forceinline__ void convert_A(char* smem, int buf, int tid) {
    const float4* xf = (const float4*)(smem + SM_XF + buf * 16384);
    __half* sAh = (__half*)(smem + SM_AH);
#pragma unroll
    for (int it = 0; it < 4; ++it) {
        int i = it * 256 + tid;
        int r = i >> 3, f = i & 7;
        float4 v = xf[i];
        uint2 hp;
        hp.x = ((uint32_t)__half_as_ushort(__float2half_rn(v.y)) << 16)
             |  __half_as_ushort(__float2half_rn(v.x));
        hp.y = ((uint32_t)__half_as_ushort(__float2half_rn(v.w)) << 16)
             |  __half_as_ushort(__float2half_rn(v.z));
        *(uint2*)(sAh + r * STR + f * 4) = hp;
    }
}

__global__ __launch_bounds__(256, 2)
void gemm_mma_kernel(const float* __restrict__ X,
                     const float* __restrict__ bias,
                     int E) {
    extern __shared__ char smem[];

    const int tid  = threadIdx.x;
    const int wid  = tid >> 5;
    const int lane = tid & 31;
    const int wm   = wid & 3;
    const int wn   = wid >> 2;
    const int rowBase = blockIdx.x * 128;

    float acc[2][8][4];
#pragma unroll
    for (int mi = 0; mi < 2; ++mi)
#pragma unroll
        for (int ni = 0; ni < 8; ++ni)
#pragma unroll
            for (int q = 0; q < 4; ++q) acc[mi][ni][q] = 0.f;

    const float4* X4  = (const float4*)X;
    const uint4*  bh4 = (const uint4*)g_wh;

    const uint32_t smb = smem_u32(smem);

    const int lrow = (lane & 7) + ((lane >> 3) & 1) * 8;
    const int lkof = ((lane >> 4) & 1) * 8;

    prefetch_chunk(smb, 0, X4, bh4, tid, rowBase, 0, E);

    for (int kc = 0; kc < IN_F / BK; ++kc) {
        const int buf = kc & 1;

        CP_WAIT0();
        __syncthreads();

        convert_A(smem, buf, tid);

        if (kc + 1 < IN_F / BK)
            prefetch_chunk(smb, buf ^ 1, X4, bh4, tid, rowBase, kc + 1, E);

        __syncthreads();

        const uint32_t ah_b = smb + SM_AH;
        const uint32_t bh_b = smb + SM_B + (uint32_t)buf * TILE_B;

#pragma unroll
        for (int ks = 0; ks < 2; ++ks) {
            const int kk = ks * 16;
            uint32_t af[2][4], bf[4][4];

#pragma unroll
            for (int mi = 0; mi < 2; ++mi)
                ldsm_x4(af[mi][0], af[mi][1], af[mi][2], af[mi][3],
                        ah_b + ((wm * 32 + mi * 16 + lrow) * STR + kk + lkof) * 2);
#pragma unroll
            for (int bi = 0; bi < 4; ++bi)
                ldsm_x4(bf[bi][0], bf[bi][1], bf[bi][2], bf[bi][3],
                        bh_b + ((wn * 64 + bi * 16 + lrow) * STR + kk + lkof) * 2);
#pragma unroll
            for (int mi = 0; mi < 2; ++mi)
#pragma unroll
                for (int bi = 0; bi < 4; ++bi) {
                    mma16816(acc[mi][bi * 2 + 0], af[mi][0], af[mi][1], af[mi][2], af[mi][3],
                             bf[bi][0], bf[bi][2]);
                    mma16816(acc[mi][bi * 2 + 1], af[mi][0], af[mi][1], af[mi][2], af[mi][3],
                             bf[bi][1], bf[bi][3]);
                }
        }
        __syncthreads();
    }

    // ---- epilogue: + bias, store fp16 t ----
    const int gid = lane >> 2;
    const int cid = (lane & 3) * 2;
#pragma unroll
    for (int mi = 0; mi < 2; ++mi) {
        int row0 = rowBase + wm * 32 + mi * 16 + gid;
#pragma unroll
        for (int ni = 0; ni < 8; ++ni) {
            int col = wn * 64 + ni * 8 + cid;
            float b0 = __ldg(bias + col), b1 = __ldg(bias + col + 1);
            if (row0 < E) {
                *(__half2*)(g_th + (size_t)row0 * HID + col) =
                    __floats2half2_rn(acc[mi][ni][0] + b0, acc[mi][ni][1] + b1);
            }
            if (row0 + 8 < E) {
                *(__half2*)(g_th + (size_t)(row0 + 8) * HID + col) =
                    __floats2half2_rn(acc[mi][ni][2] + b0, acc[mi][ni][3] + b1);
            }
        }
    }
}

// =====================================================================
// out[i] = t[i] + sum_k t[nbr[i][k]] : HADD2 balanced-tree reduction
// (30 HADD2 + 4 CVT + 4 FADD per thread vs 128 scalar ops before)
// =====================================================================
__global__ __launch_bounds__(256)
void gather_sum_kernel(const int* __restrict__ nbr,
                       float* __restrict__ out,
                       int E) {
    int gtid = blockIdx.x * blockDim.x + threadIdx.x;
    int e    = gtid >> 5;
    int lane = threadIdx.x & 31;
    if (e >= E) return;

    const uint2* H2 = (const uint2*)g_th;    // 2 half2 per uint2; 32 per row

    int j = 0;
    if (lane < 16) j = nbr[e * 16 + lane];

    uint2 s = H2[e * 32 + lane];             // self

    uint2 v[16];
#pragma unroll
    for (int k = 0; k < 16; ++k) {
        int n = __shfl_sync(0xffffffffu, j, k);
        v[k] = H2[n * 32 + lane];
    }

    // balanced fp16 tree over the 16 neighbor rows (x and y half2 lanes)
    __half2 tx[16], ty[16];
#pragma unroll
    for (int k = 0; k < 16; ++k) {
        tx[k] = *(const __half2*)&v[k].x;
        ty[k] = *(const __half2*)&v[k].y;
    }
#pragma unroll
    for (int stride = 8; stride >= 1; stride >>= 1)
#pragma unroll
        for (int k = 0; k < stride; ++k) {
            tx[k] = __hadd2(tx[k], tx[k + stride]);
            ty[k] = __hadd2(ty[k], ty[k + stride]);
        }

    // final: fp32 combine with self
    float2 fx = __half22float2(tx[0]);
    float2 fy = __half22float2(ty[0]);
    float2 sa = __half22float2(*(const __half2*)&s.x);
    float2 sb = __half22float2(*(const __half2*)&s.y);
    float4 o;
    o.x = sa.x + fx.x;
    o.y = sa.y + fx.y;
    o.z = sb.x + fy.x;
    o.w = sb.y + fy.y;
    ((float4*)out)[e * 32 + lane] = o;
}

extern "C" void kernel_launch(void* const* d_in, const int* in_sizes, int n_in,
                              void* d_out, int out_size) {
    const float* X   = (const float*)d_in[0];   // edge_feats [E, 256]
    const int*   nbr = (const int*)  d_in[1];   // neighbors  [E, 16]
    const float* W   = (const float*)d_in[2];   // W          [256, 128]
    const float* b   = (const float*)d_in[3];   // b          [128]
    float* out = (float*)d_out;                 // [E, 128]

    int E = in_sizes[0] / IN_F;

    cudaFuncSetAttribute(gemm_mma_kernel,
                         cudaFuncAttributeMaxDynamicSharedMemorySize, SMEM_BYTES);

    wconv_kernel<<<(IN_F * HID + 255) / 256, 256>>>(W);

    int gblocks = (E + 127) / 128;
    gemm_mma_kernel<<<gblocks, 256, SMEM_BYTES>>>(X, b, E);

    long long threads = (long long)E * 32;      // one warp per edge
    int blocks2 = (int)((threads + 255) / 256);
    gather_sum_kernel<<<blocks2, 256>>>(nbr, out, E);
}